// round 1
// baseline (speedup 1.0000x reference)
#include <cuda_runtime.h>
#include <cstdint>

// Problem constants
#define NROWS 16384   // B*X*Y*Z
#define DD    64
#define KCODES 8192
#define SS    4096    // X*Y*Z
#define BB    4
#define KSPLIT 4
#define TK    32      // codebook tile (codes per smem tile)
#define OUT_TENSOR_ELEMS (NROWS*DD)   // 1048576

// Scratch (device globals: allocation-free rule)
__device__ float g_latT[NROWS * DD];          // 4 MB, row-major [n][d]
__device__ float g_cbn[KCODES];               // codebook row norms
__device__ float g_pval[KSPLIT * NROWS];
__device__ int   g_pidx[KSPLIT * NROWS];
__device__ int   g_idx[NROWS];
__device__ float g_losspart[4096];

// Packed f32x2 ops (Blackwell): 2 fp32 FMAs per instruction
#define FMA2(d, a, b, c) \
    asm("fma.rn.f32x2 %0, %1, %2, %3;" : "=l"(d) : "l"(a), "l"(b), "l"(c))
#define ADD2(d, a, b) \
    asm("add.rn.f32x2 %0, %1, %2;" : "=l"(d) : "l"(a), "l"(b))
#define UNPACK2(lo, hi, p) \
    asm("mov.b64 {%0, %1}, %2;" : "=r"(lo), "=r"(hi) : "l"(p))

// ---------------------------------------------------------------------------
// K0: transpose latents [B][D][S] -> latT[(b*S+s)][d]
// ---------------------------------------------------------------------------
__global__ void k_transpose(const float* __restrict__ lat) {
    __shared__ float t[32][33];
    int b = blockIdx.z, d0 = blockIdx.y * 32, s0 = blockIdx.x * 32;
    int tx = threadIdx.x, ty = threadIdx.y;
#pragma unroll
    for (int j = 0; j < 32; j += 8)
        t[ty + j][tx] = lat[((b * DD) + (d0 + ty + j)) * SS + s0 + tx];
    __syncthreads();
#pragma unroll
    for (int j = 0; j < 32; j += 8)
        g_latT[(b * SS + s0 + ty + j) * DD + d0 + tx] = t[tx][ty + j];
}

// ---------------------------------------------------------------------------
// K0b: codebook row norms
// ---------------------------------------------------------------------------
__global__ void k_cbn(const float* __restrict__ cb) {
    int k = blockIdx.x * 256 + threadIdx.x;
    const float4* r = (const float4*)(cb + (size_t)k * DD);
    float a0 = 0.f, a1 = 0.f, a2 = 0.f, a3 = 0.f;
#pragma unroll
    for (int i = 0; i < 16; i++) {
        float4 v = r[i];
        a0 = fmaf(v.x, v.x, a0);
        a1 = fmaf(v.y, v.y, a1);
        a2 = fmaf(v.z, v.z, a2);
        a3 = fmaf(v.w, v.w, a3);
    }
    g_cbn[k] = (a0 + a1) + (a2 + a3);
}

// ---------------------------------------------------------------------------
// K1: per-row argmin over a K-split.
// One thread = one latent row (held in 32 packed f32x2 regs).
// Codebook streamed via smem tiles; all threads read same code -> LDS broadcast.
// Grid (64 rowblocks, KSPLIT), 256 thr -> 256 blocks = 1 wave @ 2 blocks/SM.
// ---------------------------------------------------------------------------
__global__ __launch_bounds__(256, 2) void k_argmin(const float* __restrict__ cb) {
    __shared__ float4 cbs[TK * 16];   // TK codes x 64 floats
    __shared__ float  cbns[TK];
    int tid = threadIdx.x;
    int n = blockIdx.x * 256 + tid;
    int k0 = blockIdx.y * (KCODES / KSPLIT);

    // Load this row as 32 packed f32x2 values
    unsigned long long la[32];
    {
        const ulonglong2* lp = (const ulonglong2*)(g_latT + (size_t)n * DD);
#pragma unroll
        for (int i = 0; i < 16; i++) {
            ulonglong2 v = lp[i];
            la[2 * i] = v.x;
            la[2 * i + 1] = v.y;
        }
    }

    // rn = ||x||^2  (packed)
    float rn;
    {
        unsigned long long r0 = 0ull, r1 = 0ull, r2 = 0ull, r3 = 0ull;
#pragma unroll
        for (int i = 0; i < 32; i += 4) {
            FMA2(r0, la[i],     la[i],     r0);
            FMA2(r1, la[i + 1], la[i + 1], r1);
            FMA2(r2, la[i + 2], la[i + 2], r2);
            FMA2(r3, la[i + 3], la[i + 3], r3);
        }
        unsigned long long s0, s1, s;
        ADD2(s0, r0, r1); ADD2(s1, r2, r3); ADD2(s, s0, s1);
        unsigned lo, hi; UNPACK2(lo, hi, s);
        rn = __uint_as_float(lo) + __uint_as_float(hi);
    }

    float best = 3.4e38f;
    int   bidx = 0;

    for (int t = 0; t < KCODES / KSPLIT; t += TK) {
        __syncthreads();
        const float4* gp = (const float4*)(cb + (size_t)(k0 + t) * DD);
        cbs[tid] = gp[tid];
        cbs[tid + 256] = gp[tid + 256];
        if (tid < TK) cbns[tid] = g_cbn[k0 + t + tid];
        __syncthreads();

#pragma unroll 4
        for (int kk = 0; kk < TK; kk++) {
            const ulonglong2* crow = (const ulonglong2*)(cbs + kk * 16);
            unsigned long long a0 = 0ull, a1 = 0ull, a2 = 0ull, a3 = 0ull;
#pragma unroll
            for (int i = 0; i < 16; i += 2) {
                ulonglong2 c0 = crow[i];
                ulonglong2 c1 = crow[i + 1];
                FMA2(a0, la[2 * i],     c0.x, a0);
                FMA2(a1, la[2 * i + 1], c0.y, a1);
                FMA2(a2, la[2 * i + 2], c1.x, a2);
                FMA2(a3, la[2 * i + 3], c1.y, a3);
            }
            unsigned long long s0, s1, s;
            ADD2(s0, a0, a1); ADD2(s1, a2, a3); ADD2(s, s0, s1);
            unsigned lo, hi; UNPACK2(lo, hi, s);
            float dot = __uint_as_float(lo) + __uint_as_float(hi);
            // Match reference rounding: dist = (rn + cn) - 2*dot, single rounding
            float dist = fmaf(-2.f, dot, rn + cbns[kk]);
            if (dist < best) { best = dist; bidx = k0 + t + kk; }
        }
    }
    g_pval[blockIdx.y * NROWS + n] = best;
    g_pidx[blockIdx.y * NROWS + n] = bidx;
}

// ---------------------------------------------------------------------------
// K2: combine split partials (ascending split order => first-index tiebreak)
// ---------------------------------------------------------------------------
__global__ void k_combine() {
    int n = blockIdx.x * 256 + threadIdx.x;
    float best = g_pval[n];
    int   bi = g_pidx[n];
#pragma unroll
    for (int sp = 1; sp < KSPLIT; sp++) {
        float v = g_pval[sp * NROWS + n];
        int   ix = g_pidx[sp * NROWS + n];
        if (v < best) { best = v; bi = ix; }
    }
    g_idx[n] = bi;
}

// ---------------------------------------------------------------------------
// K3: write output in native [B,D,S] layout (fully coalesced stores),
// gather codebook rows, deterministic block-level loss partials.
// ---------------------------------------------------------------------------
__global__ void k_outloss(const float* __restrict__ lat,
                          const float* __restrict__ cb,
                          float* __restrict__ out) {
    int e = blockIdx.x * 256 + threadIdx.x;     // 4096 blocks cover 1M elems
    int s = e & (SS - 1);
    int bd = e >> 12;
    int d = bd & (DD - 1);
    int b = bd >> 6;
    int n = b * SS + s;
    int idx = g_idx[n];
    float q = cb[(size_t)idx * DD + d];
    float l = lat[e];
    out[e] = q;
    float df = q - l;
    float v = df * df;
#pragma unroll
    for (int o = 16; o > 0; o >>= 1) v += __shfl_down_sync(0xffffffffu, v, o);
    __shared__ float red[8];
    int w = threadIdx.x >> 5, ln = threadIdx.x & 31;
    if (ln == 0) red[w] = v;
    __syncthreads();
    if (threadIdx.x < 32) {
        float x = (threadIdx.x < 8) ? red[threadIdx.x] : 0.f;
#pragma unroll
        for (int o = 4; o > 0; o >>= 1) x += __shfl_down_sync(0xffffffffu, x, o);
        if (threadIdx.x == 0) g_losspart[blockIdx.x] = x;
    }
}

// ---------------------------------------------------------------------------
// K4: final fixed-order reduce -> vq_loss = mse * (1 + w), at out[out_size-1]
// ---------------------------------------------------------------------------
__global__ void k_final(const float* __restrict__ vqw,
                        float* __restrict__ out, int out_size) {
    __shared__ float sm[256];
    int tid = threadIdx.x;
    float a = 0.f;
#pragma unroll
    for (int i = 0; i < 16; i++) a += g_losspart[tid * 16 + i];
    sm[tid] = a;
    __syncthreads();
    for (int o = 128; o > 0; o >>= 1) {
        if (tid < o) sm[tid] += sm[tid + o];
        __syncthreads();
    }
    if (tid == 0 && out_size > OUT_TENSOR_ELEMS) {
        float w = vqw[0];
        out[out_size - 1] = sm[0] * (1.f + w) * (1.f / (float)OUT_TENSOR_ELEMS);
    }
}

// ---------------------------------------------------------------------------
extern "C" void kernel_launch(void* const* d_in, const int* in_sizes, int n_in,
                              void* d_out, int out_size) {
    const float* lat = (const float*)d_in[0];   // latents [4,64,16,16,16] f32
    const float* vqw = (const float*)d_in[1];   // vq_weight scalar f32
    const float* cb  = (const float*)d_in[2];   // codebook [8192,64] f32
    float* out = (float*)d_out;

    k_transpose<<<dim3(SS / 32, DD / 32, BB), dim3(32, 8)>>>(lat);
    k_cbn<<<KCODES / 256, 256>>>(cb);
    k_argmin<<<dim3(NROWS / 256, KSPLIT), 256>>>(cb);
    k_combine<<<NROWS / 256, 256>>>();
    k_outloss<<<OUT_TENSOR_ELEMS / 256, 256>>>(lat, cb, out);
    k_final<<<1, 256>>>(vqw, out, out_size);
}